// round 4
// baseline (speedup 1.0000x reference)
#include <cuda_runtime.h>
#include <cuda_bf16.h>
#include <cstdint>

#define BATCH 8
#define MDIM  2048
#define LDIM  2048
#define HDIM  1024

typedef __nv_bfloat16 bf16;

// ---------------------------------------------------------------------------
// Scratch (module-load allocated; runtime allocs forbidden).
// ---------------------------------------------------------------------------
__device__ bf16 g_KhiT[(size_t)BATCH * HDIM * LDIM];  // [B,H,L]
__device__ bf16 g_KloT[(size_t)BATCH * HDIM * LDIM];
__device__ bf16 g_VhiT[(size_t)BATCH * HDIM * LDIM];  // [B,H,L] (rows j, k=l)
__device__ bf16 g_VloT[(size_t)BATCH * HDIM * LDIM];
__device__ bf16 g_Qhi [(size_t)BATCH * MDIM * HDIM];  // [B,M,H]
__device__ bf16 g_Qlo [(size_t)BATCH * MDIM * HDIM];
__device__ bf16 g_Thi [(size_t)BATCH * HDIM * HDIM];  // [B,H,H] rows h, cols j
__device__ bf16 g_Tlo [(size_t)BATCH * HDIM * HDIM];

// ---------------------------------------------------------------------------
// Baseline-ISA (sm_80+) PTX helpers: ldmatrix / mma.sync / cp.async.
// (tcgen05 is unavailable: harness PTX targets compute_103, not compute_103a.)
// ---------------------------------------------------------------------------
__device__ __forceinline__ uint32_t smem_u32(const void* p) {
    uint32_t a;
    asm("{ .reg .u64 t; cvta.to.shared.u64 t, %1; cvt.u32.u64 %0, t; }"
        : "=r"(a) : "l"(p));
    return a;
}
__device__ __forceinline__ void cp16(uint32_t dst, const void* src) {
    asm volatile("cp.async.cg.shared.global [%0], [%1], 16;"
                 :: "r"(dst), "l"(src) : "memory");
}
__device__ __forceinline__ void cp_commit() {
    asm volatile("cp.async.commit_group;" ::: "memory");
}
__device__ __forceinline__ void cp_wait1() {
    asm volatile("cp.async.wait_group 1;" ::: "memory");
}
__device__ __forceinline__ void cp_wait0() {
    asm volatile("cp.async.wait_group 0;" ::: "memory");
}
__device__ __forceinline__ void ldsm_x4(uint32_t a, uint32_t& r0, uint32_t& r1,
                                        uint32_t& r2, uint32_t& r3) {
    asm volatile("ldmatrix.sync.aligned.m8n8.x4.shared.b16 {%0,%1,%2,%3}, [%4];"
                 : "=r"(r0), "=r"(r1), "=r"(r2), "=r"(r3) : "r"(a));
}
__device__ __forceinline__ void ldsm_x4_t(uint32_t a, uint32_t& r0, uint32_t& r1,
                                          uint32_t& r2, uint32_t& r3) {
    asm volatile("ldmatrix.sync.aligned.m8n8.x4.trans.shared.b16 {%0,%1,%2,%3}, [%4];"
                 : "=r"(r0), "=r"(r1), "=r"(r2), "=r"(r3) : "r"(a));
}
__device__ __forceinline__ void mma_bf16(float* d, const uint32_t* a,
                                         const uint32_t* b) {
    asm volatile(
        "mma.sync.aligned.m16n8k16.row.col.f32.bf16.bf16.f32 "
        "{%0,%1,%2,%3}, {%4,%5,%6,%7}, {%8,%9}, {%0,%1,%2,%3};"
        : "+f"(d[0]), "+f"(d[1]), "+f"(d[2]), "+f"(d[3])
        : "r"(a[0]), "r"(a[1]), "r"(a[2]), "r"(a[3]), "r"(b[0]), "r"(b[1]));
}

// ---------------------------------------------------------------------------
// GEMM: D(128x128 f32) = sum over 3 split terms of A @ B^T
//   A [rows=m][k] row-major (k-contiguous), tiles BM=128 x BK=32
//   TRANSB=0: B given as Bt [rows=n][k]   (tile [128][32], non-trans ldmatrix)
//   TRANSB=1: B given as B  [rows=k][n]   (tile [32][128], trans ldmatrix)
//   FOUT=1: fp32 store; FOUT=0: split hi/lo bf16 store.
// 8 warps (2m x 4n), warp tile 64x32, 3-stage cp.async pipeline.
// ---------------------------------------------------------------------------
#define BK 32
#define A_STRIDE 80u              /* 32 bf16 = 64B, padded to 80B */
#define BT_STRIDE 272u            /* 128 bf16 = 256B, padded to 272B */
#define A_SZ (128u * A_STRIDE)    /* 10240 */
#define BNT_SZ (128u * A_STRIDE)  /* 10240 */
#define BT_SZ (32u * BT_STRIDE)   /* 8704  */

template <int TRANSB, int FOUT>
__global__ __launch_bounds__(256) void mma_gemm(
    const bf16* __restrict__ Ahi, const bf16* __restrict__ Alo,
    size_t bsA, int lda,
    const bf16* __restrict__ Bhi, const bf16* __restrict__ Blo,
    size_t bsB, int ldb,
    int Kdim,
    bf16* __restrict__ outHi, bf16* __restrict__ outLo,
    float* __restrict__ outF, size_t bsO, int ldo)
{
    extern __shared__ __align__(128) char dsm[];
    const uint32_t tb = smem_u32(dsm);
    const uint32_t BSZ = TRANSB ? BT_SZ : BNT_SZ;
    const uint32_t STAGE = A_SZ + BSZ;

    const int tid = threadIdx.x;
    const int lane = tid & 31, wid = tid >> 5;
    const int wm = wid >> 2, wn = wid & 3;  // 2 x 4 warp grid

    const int b = blockIdx.z;
    const int m0 = blockIdx.y * 128, n0 = blockIdx.x * 128;

    const bf16* Abh = Ahi + (size_t)b * bsA + (size_t)m0 * lda;
    const bf16* Abl = Alo + (size_t)b * bsA + (size_t)m0 * lda;
    const bf16* Bbh;
    const bf16* Bbl;
    if (TRANSB) { Bbh = Bhi + (size_t)b * bsB + n0; Bbl = Blo + (size_t)b * bsB + n0; }
    else        { Bbh = Bhi + (size_t)b * bsB + (size_t)n0 * ldb;
                  Bbl = Blo + (size_t)b * bsB + (size_t)n0 * ldb; }

    const int KC = Kdim >> 5;       // chunks per term
    const int NC = 3 * KC;          // total chunks (hi*hi, lo*hi, hi*lo)

    float d[4][4][4];
#pragma unroll
    for (int i = 0; i < 4; i++)
#pragma unroll
        for (int j = 0; j < 4; j++)
#pragma unroll
            for (int e = 0; e < 4; e++) d[i][j][e] = 0.0f;

    // ---- per-chunk async load ----
    auto issue = [&](int c) {
        const int term = c / KC;
        const int k0 = (c - term * KC) << 5;
        const bf16* A = (term == 1) ? Abl : Abh;
        const bf16* B = (term == 2) ? Bbl : Bbh;
        const uint32_t sA = tb + (uint32_t)(c % 3) * STAGE;
        const uint32_t sB = sA + A_SZ;
        {   // A tile 128x32 -> 512 x 16B, 2 per thread (contiguous pair)
            const int q = tid << 1;
            const int row = q >> 2, c0 = q & 3;
            const bf16* src = A + (size_t)row * lda + k0 + c0 * 8;
            const uint32_t dst = sA + row * A_STRIDE + c0 * 16;
            cp16(dst, src);
            cp16(dst + 16, src + 8);
        }
        if (TRANSB) {  // B tile 32x128
            const int q = tid << 1;
            const int row = q >> 4, c0 = q & 15;
            const bf16* src = B + (size_t)(k0 + row) * ldb + c0 * 8;
            const uint32_t dst = sB + row * BT_STRIDE + c0 * 16;
            cp16(dst, src);
            cp16(dst + 16, src + 8);
        } else {       // Bt tile 128x32
            const int q = tid << 1;
            const int row = q >> 2, c0 = q & 3;
            const bf16* src = B + (size_t)row * ldb + k0 + c0 * 8;
            const uint32_t dst = sB + row * A_STRIDE + c0 * 16;
            cp16(dst, src);
            cp16(dst + 16, src + 8);
        }
        cp_commit();
    };

    issue(0);
    issue(1);

    for (int c = 0; c < NC; c++) {
        if (c + 2 < NC) cp_wait1(); else cp_wait0();
        __syncthreads();
        if (c + 2 < NC) issue(c + 2);

        const uint32_t sA = tb + (uint32_t)(c % 3) * STAGE;
        const uint32_t sB = sA + A_SZ;

#pragma unroll
        for (int ks = 0; ks < 2; ks++) {
            // B fragments: 2 x ldmatrix.x4 covering 32 n-cols
            uint32_t bfr[2][4];
#pragma unroll
            for (int nj = 0; nj < 2; nj++) {
                uint32_t addr;
                if (TRANSB) {
                    const int krow = ks * 16 + (lane & 15);
                    const int nbyte = (wn * 32 + nj * 16 + ((lane >> 4) << 3)) * 2;
                    addr = sB + krow * BT_STRIDE + nbyte;
                } else {
                    const int nrow = wn * 32 + nj * 16 + (lane & 7) + ((lane >> 4) << 3);
                    const int koff = ks * 32 + 16 * ((lane >> 3) & 1);
                    addr = sB + nrow * A_STRIDE + koff;
                }
                if (TRANSB) ldsm_x4_t(addr, bfr[nj][0], bfr[nj][1], bfr[nj][2], bfr[nj][3]);
                else        ldsm_x4  (addr, bfr[nj][0], bfr[nj][1], bfr[nj][2], bfr[nj][3]);
            }
            // A fragments + MMAs
#pragma unroll
            for (int mi = 0; mi < 4; mi++) {
                uint32_t afr[4];
                const int arow = wm * 64 + mi * 16 + (lane & 15);
                const int akoff = ks * 32 + ((lane >> 4) << 4);
                ldsm_x4(sA + arow * A_STRIDE + akoff, afr[0], afr[1], afr[2], afr[3]);
#pragma unroll
                for (int nj = 0; nj < 2; nj++) {
                    mma_bf16(d[mi][nj * 2 + 0], afr, &bfr[nj][0]);
                    mma_bf16(d[mi][nj * 2 + 1], afr, &bfr[nj][2]);
                }
            }
        }
    }

    // ---- epilogue ----
    const int rbase = m0 + wm * 64 + (lane >> 2);
    const int cbase = n0 + wn * 32 + 2 * (lane & 3);
#pragma unroll
    for (int mi = 0; mi < 4; mi++) {
#pragma unroll
        for (int ni = 0; ni < 4; ni++) {
#pragma unroll
            for (int h = 0; h < 2; h++) {  // h=0: rows +0, h=1: rows +8
                const int gr = rbase + mi * 16 + h * 8;
                const int gc = cbase + ni * 8;
                const float v0 = d[mi][ni][h * 2 + 0];
                const float v1 = d[mi][ni][h * 2 + 1];
                if (FOUT) {
                    float2 f2 = make_float2(v0, v1);
                    *reinterpret_cast<float2*>(
                        outF + (size_t)b * bsO + (size_t)gr * ldo + gc) = f2;
                } else {
                    bf16 h0 = __float2bfloat16(v0);
                    bf16 h1 = __float2bfloat16(v1);
                    bf16 l0 = __float2bfloat16(v0 - __bfloat162float(h0));
                    bf16 l1 = __float2bfloat16(v1 - __bfloat162float(h1));
                    const size_t off = (size_t)b * bsO + (size_t)gr * ldo + gc;
                    *reinterpret_cast<__nv_bfloat162*>(outHi + off) = __nv_bfloat162(h0, h1);
                    *reinterpret_cast<__nv_bfloat162*>(outLo + off) = __nv_bfloat162(l0, l1);
                }
            }
        }
    }
}

// ---------------------------------------------------------------------------
// Conversion kernels
// ---------------------------------------------------------------------------
__global__ __launch_bounds__(256) void split_kernel(const float* __restrict__ in,
                                                    bf16* __restrict__ hi,
                                                    bf16* __restrict__ lo)
{
    size_t idx = (size_t)blockIdx.x * blockDim.x + threadIdx.x;  // float4 index
    float4 v = reinterpret_cast<const float4*>(in)[idx];
    float f[4] = {v.x, v.y, v.z, v.w};
    __nv_bfloat162 h2[2], l2[2];
#pragma unroll
    for (int p = 0; p < 2; p++) {
        bf16 h0 = __float2bfloat16(f[2 * p]);
        bf16 h1 = __float2bfloat16(f[2 * p + 1]);
        bf16 l0 = __float2bfloat16(f[2 * p] - __bfloat162float(h0));
        bf16 l1 = __float2bfloat16(f[2 * p + 1] - __bfloat162float(h1));
        h2[p] = __nv_bfloat162(h0, h1);
        l2[p] = __nv_bfloat162(l0, l1);
    }
    reinterpret_cast<__nv_bfloat162*>(hi)[idx * 2 + 0] = h2[0];
    reinterpret_cast<__nv_bfloat162*>(hi)[idx * 2 + 1] = h2[1];
    reinterpret_cast<__nv_bfloat162*>(lo)[idx * 2 + 0] = l2[0];
    reinterpret_cast<__nv_bfloat162*>(lo)[idx * 2 + 1] = l2[1];
}

// K/V: [B,L,H] fp32 -> transposed [B,H,L] bf16 hi/lo (32x32 smem tile).
__global__ __launch_bounds__(256) void tsplit_kernel(const float* __restrict__ in,
                                                     bf16* __restrict__ hiT,
                                                     bf16* __restrict__ loT)
{
    __shared__ float tile[32][33];
    const int b = blockIdx.z;
    const int h0 = blockIdx.x * 32, l0 = blockIdx.y * 32;
    const int tx = threadIdx.x, ty = threadIdx.y;  // (32, 8)

    const float* src = in + (size_t)b * LDIM * HDIM;
#pragma unroll
    for (int k = 0; k < 4; k++)
        tile[ty + k * 8][tx] = src[(size_t)(l0 + ty + k * 8) * HDIM + h0 + tx];
    __syncthreads();

    const size_t obase = (size_t)b * HDIM * LDIM;
#pragma unroll
    for (int k = 0; k < 4; k++) {
        int hh = h0 + ty + k * 8;
        int ll = l0 + tx;
        float v = tile[tx][ty + k * 8];
        bf16 h = __float2bfloat16(v);
        bf16 l = __float2bfloat16(v - __bfloat162float(h));
        size_t off = obase + (size_t)hh * LDIM + ll;
        hiT[off] = h;
        loT[off] = l;
    }
}

// ---------------------------------------------------------------------------
// Launch: out = Q @ (K^T @ V), split-bf16 mma.sync path.
// key_pe / hidden_size are dead inputs (softmax & attn_pos are dead code).
// ---------------------------------------------------------------------------
#define SMEM_NT (3 * (A_SZ + BNT_SZ))  /* 61440 */
#define SMEM_T  (3 * (A_SZ + BT_SZ))   /* 56832 */

extern "C" void kernel_launch(void* const* d_in, const int* in_sizes, int n_in,
                              void* d_out, int out_size)
{
    const float* q = (const float*)d_in[0];  // [B, M, H]
    const float* k = (const float*)d_in[1];  // [B, L, H]
    const float* v = (const float*)d_in[2];  // [B, L, H]
    float* out = (float*)d_out;              // [B, M, H]

    cudaFuncSetAttribute(mma_gemm<0, 0>,
                         cudaFuncAttributeMaxDynamicSharedMemorySize, SMEM_NT);
    cudaFuncSetAttribute(mma_gemm<1, 1>,
                         cudaFuncAttributeMaxDynamicSharedMemorySize, SMEM_T);

    // 1) splits / transposes
    {
        size_t n4 = (size_t)BATCH * MDIM * HDIM / 4;
        split_kernel<<<(unsigned)(n4 / 256), 256>>>(q, g_Qhi, g_Qlo);
        dim3 tg(HDIM / 32, LDIM / 32, BATCH);
        dim3 tb(32, 8);
        tsplit_kernel<<<tg, tb>>>(k, g_KhiT, g_KloT);
        tsplit_kernel<<<tg, tb>>>(v, g_VhiT, g_VloT);
    }

    // 2) T[h][j] = sum_l K^T[h][l] * V^T[j][l]   (A = K^T, Bt = V^T, TRANSB=0)
    {
        dim3 g1(HDIM / 128, HDIM / 128, BATCH);
        mma_gemm<0, 0><<<g1, 256, SMEM_NT>>>(
            g_KhiT, g_KloT, (size_t)HDIM * LDIM, LDIM,
            g_VhiT, g_VloT, (size_t)HDIM * LDIM, LDIM,
            LDIM,
            g_Thi, g_Tlo, nullptr, (size_t)HDIM * HDIM, HDIM);
    }

    // 3) O[m][j] = sum_h Q[m][h] * T[h][j]       (A = Q, B = T rows=k, TRANSB=1)
    {
        dim3 g2(HDIM / 128, MDIM / 128, BATCH);
        mma_gemm<1, 1><<<g2, 256, SMEM_T>>>(
            g_Qhi, g_Qlo, (size_t)MDIM * HDIM, HDIM,
            g_Thi, g_Tlo, (size_t)HDIM * HDIM, HDIM,
            HDIM,
            nullptr, nullptr, out, (size_t)MDIM * HDIM, HDIM);
    }
}

// round 6
// speedup vs baseline: 3.3735x; 3.3735x over previous
#include <cuda_runtime.h>
#include <cstdint>

#define BATCH 8
#define MDIM  2048
#define LDIM  2048
#define HDIM  1024
#define BK    16

typedef unsigned long long u64;

// Scratch (module-load allocated; runtime allocs forbidden)
__device__ float g_T [(size_t)BATCH * HDIM * HDIM];  // T = K^T V   [B,H,H]
__device__ float g_Qt[(size_t)BATCH * HDIM * MDIM];  // Q^T         [B,H,M]

// ---------------------------------------------------------------------------
// helpers
// ---------------------------------------------------------------------------
__device__ __forceinline__ uint32_t smem_u32(const void* p) {
    uint32_t a;
    asm("{ .reg .u64 t; cvta.to.shared.u64 t, %1; cvt.u32.u64 %0, t; }"
        : "=r"(a) : "l"(p));
    return a;
}
__device__ __forceinline__ void cp16(uint32_t dst, const void* src) {
    asm volatile("cp.async.cg.shared.global [%0], [%1], 16;"
                 :: "r"(dst), "l"(src) : "memory");
}
__device__ __forceinline__ void cp_commit() {
    asm volatile("cp.async.commit_group;" ::: "memory");
}
__device__ __forceinline__ void cp_wait1() {
    asm volatile("cp.async.wait_group 1;" ::: "memory");
}
__device__ __forceinline__ void cp_wait0() {
    asm volatile("cp.async.wait_group 0;" ::: "memory");
}
// Blackwell packed fp32x2 FMA (baseline sm_100+ PTX, works under compute_103)
__device__ __forceinline__ u64 pack2(float a) {
    u64 r;
    asm("mov.b64 %0, {%1, %1};" : "=l"(r) : "f"(a));
    return r;
}
__device__ __forceinline__ void ffma2(u64& d, u64 a, u64 b) {
    asm("fma.rn.f32x2 %0, %1, %2, %0;" : "+l"(d) : "l"(a), "l"(b));
}

// ---------------------------------------------------------------------------
// Generic "TN-free" GEMM: C[m][n] = sum_k A[k][m] * B[k][n]
// A rows k-major (ldA), B rows k-major (ldB). 128x128 tile, BK=16,
// 256 threads, 8x8 per-thread micro-tile as 8x4 packed f32x2,
// 3-stage cp.async pipeline (3 x 16KB smem).
// ---------------------------------------------------------------------------
__global__ __launch_bounds__(256, 2) void sgemm_tn(
    const float* __restrict__ Ap, int lda, size_t bsA,
    const float* __restrict__ Bp, int ldb, size_t bsB,
    float* __restrict__ Cp, int ldc, size_t bsC,
    int Kdim)
{
    extern __shared__ __align__(16) float sm[];
    const uint32_t tb = smem_u32(sm);

    const int tid = threadIdx.x;
    const int ty = tid >> 4, tx = tid & 15;
    const int b = blockIdx.z;
    const int m0 = blockIdx.y * 128, n0 = blockIdx.x * 128;

    const float* A = Ap + (size_t)b * bsA;
    const float* B = Bp + (size_t)b * bsB;

    u64 acc[8][4];
#pragma unroll
    for (int i = 0; i < 8; i++)
#pragma unroll
        for (int j = 0; j < 4; j++) acc[i][j] = 0ull;

    // per-chunk async load: 16 rows x 128 cols per matrix = 512 x 16B,
    // 2 segments per thread per matrix.
    auto issue = [&](int it) {
        const uint32_t s = tb + (uint32_t)(it % 3) * 16384u;
        const int k0 = it * BK;
#pragma unroll
        for (int h = 0; h < 2; h++) {
            const int seg = tid + h * 256;          // 0..511
            const int row = seg >> 5;               // 0..15
            const int c4  = seg & 31;               // float4 within row
            const uint32_t off = (uint32_t)(row * 512 + c4 * 16);
            cp16(s + off,         A + (size_t)(k0 + row) * lda + m0 + c4 * 4);
            cp16(s + 8192u + off, B + (size_t)(k0 + row) * ldb + n0 + c4 * 4);
        }
        cp_commit();
    };

    const int NK = Kdim / BK;
    issue(0);
    issue(1);

    for (int c = 0; c < NK; c++) {
        if (c + 2 < NK) cp_wait1(); else cp_wait0();
        __syncthreads();
        if (c + 2 < NK) issue(c + 2);

        const float* As = sm + (size_t)(c % 3) * 4096;  // floats
        const float* Bs = As + 2048;

#pragma unroll
        for (int k = 0; k < BK; k++) {
            float4 a0 = *(const float4*)(As + k * 128 + ty * 8);
            float4 a1 = *(const float4*)(As + k * 128 + ty * 8 + 4);
            ulonglong2 p0 = *(const ulonglong2*)(Bs + k * 128 + tx * 8);
            ulonglong2 p1 = *(const ulonglong2*)(Bs + k * 128 + tx * 8 + 4);
            const float av[8] = {a0.x, a0.y, a0.z, a0.w, a1.x, a1.y, a1.z, a1.w};
#pragma unroll
            for (int i = 0; i < 8; i++) {
                const u64 aa = pack2(av[i]);
                ffma2(acc[i][0], aa, p0.x);
                ffma2(acc[i][1], aa, p0.y);
                ffma2(acc[i][2], aa, p1.x);
                ffma2(acc[i][3], aa, p1.y);
            }
        }
    }

    // epilogue: packed pairs are directly the (n, n+1) layout -> 2x 16B stores/row
#pragma unroll
    for (int i = 0; i < 8; i++) {
        float* crow = Cp + (size_t)b * bsC + (size_t)(m0 + ty * 8 + i) * ldc + n0 + tx * 8;
        ulonglong2 v0; v0.x = acc[i][0]; v0.y = acc[i][1];
        ulonglong2 v1; v1.x = acc[i][2]; v1.y = acc[i][3];
        *reinterpret_cast<ulonglong2*>(crow)     = v0;
        *reinterpret_cast<ulonglong2*>(crow + 4) = v1;
    }
}

// ---------------------------------------------------------------------------
// Q transpose: [B,M,H] -> [B,H,M]  (32x32 smem tiles)
// ---------------------------------------------------------------------------
__global__ __launch_bounds__(256) void transpose_q(const float* __restrict__ in,
                                                   float* __restrict__ out)
{
    __shared__ float t[32][33];
    const int b = blockIdx.z;
    const int h0 = blockIdx.x * 32, m0 = blockIdx.y * 32;
    const int tx = threadIdx.x, ty = threadIdx.y;  // (32, 8)

    const float* src = in + (size_t)b * MDIM * HDIM;
#pragma unroll
    for (int k = 0; k < 4; k++)
        t[ty + k * 8][tx] = src[(size_t)(m0 + ty + k * 8) * HDIM + h0 + tx];
    __syncthreads();

    float* dst = out + (size_t)b * HDIM * MDIM;
#pragma unroll
    for (int k = 0; k < 4; k++)
        dst[(size_t)(h0 + ty + k * 8) * MDIM + m0 + tx] = t[tx][ty + k * 8];
}

// ---------------------------------------------------------------------------
// Launch: out = Q @ (K^T @ V). key_pe / hidden_size are dead inputs
// (attn_pos and the softmax are dead code in the reference).
// ---------------------------------------------------------------------------
#define GEMM_SMEM 49152

extern "C" void kernel_launch(void* const* d_in, const int* in_sizes, int n_in,
                              void* d_out, int out_size)
{
    const float* q = (const float*)d_in[0];  // [B, M, H]
    const float* k = (const float*)d_in[1];  // [B, L, H]
    const float* v = (const float*)d_in[2];  // [B, L, H]
    float* out = (float*)d_out;              // [B, M, H]

    cudaFuncSetAttribute(sgemm_tn, cudaFuncAttributeMaxDynamicSharedMemorySize,
                         GEMM_SMEM);

    // 0) Q^T so stage-2 A-tiles are k-major contiguous
    {
        dim3 g(HDIM / 32, MDIM / 32, BATCH), tB(32, 8);
        transpose_q<<<g, tB>>>(q, g_Qt);
    }

    // 1) T[i][j] = sum_l K[l][i] V[l][j]   (A=K rows l, B=V rows l)
    {
        dim3 g1(HDIM / 128, HDIM / 128, BATCH);
        sgemm_tn<<<g1, 256, GEMM_SMEM>>>(
            k, HDIM, (size_t)LDIM * HDIM,
            v, HDIM, (size_t)LDIM * HDIM,
            g_T, HDIM, (size_t)HDIM * HDIM,
            LDIM);
    }

    // 2) O[m][j] = sum_h Qt[h][m] T[h][j]  (A=Qt rows h, B=T rows h)
    {
        dim3 g2(HDIM / 128, MDIM / 128, BATCH);
        sgemm_tn<<<g2, 256, GEMM_SMEM>>>(
            g_Qt, MDIM, (size_t)HDIM * MDIM,
            g_T, HDIM, (size_t)HDIM * HDIM,
            out, HDIM, (size_t)MDIM * HDIM,
            HDIM);
    }
}